// round 9
// baseline (speedup 1.0000x reference)
#include <cuda_runtime.h>
#include <math.h>

#define NB 32768
#define ND 1024
#define NC 256
#define PAD 1024
#define CH 14
#define NCHUNK ((NB + CH - 1) / CH)   // 2341
#define DEPTH 2
#define LOSS_WEIGHT 0.0005
#define EPSN 1e-12f

// ---- static scratch (zero at load; invariants restored in-pipeline) ----
__device__ int    g_cnt[NC];                 // 0 at entry
__device__ int    g_off[NC];
__device__ int    g_cursor[NC];
__device__ int    g_flat[NB];
__device__ int    g_sorted[NB];
__device__ float  g_sums[NC * ND];           // S_c, accumulated via REDG
__device__ float  g_nf2[NC];
__device__ float  g_s2[NC];
__device__ double g_accum;                   // 0 at entry
__device__ int    g_done1;                   // 0 at entry
__device__ int    g_done2;                   // 0 at entry

// ---- K0: zero accumulators ----
__global__ __launch_bounds__(1024) void k_pre() {
    int t = blockIdx.x * 1024 + threadIdx.x;
    ((float4*)g_sums)[t * 2] = make_float4(0.f, 0.f, 0.f, 0.f);
    ((float4*)g_sums)[t * 2 + 1] = make_float4(0.f, 0.f, 0.f, 0.f);
    if (t < NC) g_nf2[t] = 0.f;
}

// ---- K1: histogram; last block computes prefix + zeroes cursors ----
__global__ __launch_bounds__(1024) void k_hist(const int* __restrict__ lab) {
    __shared__ int scnt[NC];
    int t = threadIdx.x;
    if (t < NC) scnt[t] = 0;
    __syncthreads();
    atomicAdd(&scnt[lab[blockIdx.x * 1024 + t]], 1);
    __syncthreads();
    if (t < NC && scnt[t]) atomicAdd(&g_cnt[t], scnt[t]);
    __threadfence();
    __shared__ int islast;
    if (t == 0) islast = (atomicAdd(&g_done1, 1) == (int)gridDim.x - 1);
    __syncthreads();
    if (!islast) return;
    __shared__ int s[NC];
    int v = 0;
    if (t < NC) { v = g_cnt[t]; s[t] = v; }
    __syncthreads();
    for (int o = 1; o < NC; o <<= 1) {
        int add = (t < NC && t >= o) ? s[t - o] : 0;
        __syncthreads();
        if (t < NC) s[t] += add;
        __syncthreads();
    }
    if (t < NC) { g_off[t] = s[t] - v; g_cursor[t] = 0; }
    if (t == 0) g_done1 = 0;
}

// ---- K2: block-aggregated scatter into flat class-sorted list ----
__global__ __launch_bounds__(1024) void k_scatter(const int* __restrict__ lab) {
    __shared__ int scnt[NC];
    __shared__ int sbase[NC];
    int t = threadIdx.x;
    if (t < NC) scnt[t] = 0;
    __syncthreads();
    int row = blockIdx.x * 1024 + t;
    int c = lab[row];
    int r = atomicAdd(&scnt[c], 1);
    __syncthreads();
    if (t < NC && scnt[t]) sbase[t] = atomicAdd(&g_cursor[t], scnt[t]);
    __syncthreads();
    g_flat[g_off[c] + sbase[c] + r] = row;
}

// ---- K3 (profiled slot 4): fused norms + atomic class sums; warp = 14 rows ----
// DEPTH=2 cp.async ring (32KB/block), smem re-read instead of register copy.
__global__ __launch_bounds__(128, 6) void k_fused(const float* __restrict__ x,
                                                  const int* __restrict__ lab) {
    __shared__ float4 ring[4][DEPTH][256];   // 32KB
    int t = threadIdx.x, lane = t & 31, w = t >> 5;
    int g = blockIdx.x * 4 + w;
    int r0 = g * CH;
    int cnt = 0;
    if (r0 < NB) { cnt = NB - r0; if (cnt > CH) cnt = CH; }

    int idx = 0, cl = -1;
    if (lane < cnt) { idx = g_flat[r0 + lane]; cl = lab[idx]; }

    const float4* xb = (const float4*)x;
    unsigned smem_base = (unsigned)__cvta_generic_to_shared(&ring[w][0][lane]);

#pragma unroll
    for (int s = 0; s < DEPTH; s++) {
        if (s < cnt) {
            int is = __shfl_sync(0xFFFFFFFFu, idx, s);
            const float4* src = xb + (size_t)is * 256 + lane;
            unsigned d = smem_base + s * 4096;
#pragma unroll
            for (int k = 0; k < 8; k++)
                asm volatile("cp.async.cg.shared.global [%0], [%1], 16;"
                             :: "r"(d + k * 512), "l"(src + k * 32));
        }
        asm volatile("cp.async.commit_group;");
    }

    float4 acc[8];
#pragma unroll
    for (int k = 0; k < 8; k++) acc[k] = make_float4(0.f, 0.f, 0.f, 0.f);
    float nf2 = 0.f;
    int cur = __shfl_sync(0xFFFFFFFFu, cl, 0);
    int st = 0;

    for (int j = 0; j < cnt; j++) {
        asm volatile("cp.async.wait_group %0;" :: "n"(DEPTH - 1));

        // pass 1: row sum-of-squares (values stay short-lived)
        float ss = 0.f;
#pragma unroll
        for (int k = 0; k < 8; k++) {
            float4 v = ring[w][st][k * 32 + lane];
            ss += v.x * v.x + v.y * v.y + v.z * v.z + v.w * v.w;
        }
#pragma unroll
        for (int o = 16; o; o >>= 1) ss += __shfl_xor_sync(0xFFFFFFFFu, ss, o);
        float inv = 1.0f / fmaxf(sqrtf(ss), EPSN);

        int cj = __shfl_sync(0xFFFFFFFFu, cl, j);
        if (cj != cur) {                     // class boundary: flush to atomics
            float* dst = g_sums + (size_t)cur * ND;
#pragma unroll
            for (int k = 0; k < 8; k++) {
                int d0 = k * 128 + lane * 4;
                atomicAdd(&dst[d0 + 0], acc[k].x);
                atomicAdd(&dst[d0 + 1], acc[k].y);
                atomicAdd(&dst[d0 + 2], acc[k].z);
                atomicAdd(&dst[d0 + 3], acc[k].w);
            }
            if (lane == 0) atomicAdd(&g_nf2[cur], nf2);
#pragma unroll
            for (int k = 0; k < 8; k++) acc[k] = make_float4(0.f, 0.f, 0.f, 0.f);
            nf2 = 0.f; cur = cj;
        }

        // pass 2: re-read smem row, accumulate normalized values
#pragma unroll
        for (int k = 0; k < 8; k++) {
            float4 v = ring[w][st][k * 32 + lane];
            acc[k].x += v.x * inv; acc[k].y += v.y * inv;
            acc[k].z += v.z * inv; acc[k].w += v.w * inv;
        }
        nf2 += ss * inv * inv;

        int jn = j + DEPTH;
        if (jn < cnt) {
            int in = __shfl_sync(0xFFFFFFFFu, idx, jn);
            const float4* src = xb + (size_t)in * 256 + lane;
            unsigned d = smem_base + st * 4096;
#pragma unroll
            for (int k = 0; k < 8; k++)
                asm volatile("cp.async.cg.shared.global [%0], [%1], 16;"
                             :: "r"(d + k * 512), "l"(src + k * 32));
        }
        asm volatile("cp.async.commit_group;");
        st ^= 1;
    }
    if (cnt > 0) {
        float* dst = g_sums + (size_t)cur * ND;
#pragma unroll
        for (int k = 0; k < 8; k++) {
            int d0 = k * 128 + lane * 4;
            atomicAdd(&dst[d0 + 0], acc[k].x);
            atomicAdd(&dst[d0 + 1], acc[k].y);
            atomicAdd(&dst[d0 + 2], acc[k].z);
            atomicAdd(&dst[d0 + 3], acc[k].w);
        }
        if (lane == 0) atomicAdd(&g_nf2[cur], nf2);
    }
}

// ---- K4: ||S_c||^2 + base contribution; sort member ranks ----
__global__ __launch_bounds__(256) void k_comb() {
    int c = blockIdx.x, t = threadIdx.x;
    int n = g_cnt[c];
    if (n == 0) return;
    int off = g_off[c];

    float4 s = ((const float4*)(g_sums + (size_t)c * ND))[t];
    float sq = s.x * s.x + s.y * s.y + s.z * s.z + s.w * s.w;
#pragma unroll
    for (int o = 16; o; o >>= 1) sq += __shfl_xor_sync(0xFFFFFFFFu, sq, o);
    __shared__ float sred[8];
    int lane = t & 31, w = t >> 5;
    if (lane == 0) sred[w] = sq;

    __shared__ int sm_m[PAD];
    for (int j = t; j < n; j += 256) sm_m[j] = g_flat[off + j];
    __syncthreads();
    for (int j = t; j < n; j += 256) {
        int mj = sm_m[j];
        int rank = 0;
        for (int u = 0; u < n; u++) rank += (sm_m[u] < mj);
        g_sorted[off + rank] = mj;
    }

    if (t == 0) {
        float s2 = 0.f;
#pragma unroll
        for (int u = 0; u < 8; u++) s2 += sred[u];
        g_s2[c] = s2;
        if (n > 1) {
            double base = ((double)g_nf2[c] - (double)s2 / (double)n) / (double)ND;
            atomicAdd(&g_accum, base);
        }
    }
}

// ---- K5: exclusion corrections; last block finalizes + restores invariants ----
__global__ __launch_bounds__(128) void k_corr(const float* __restrict__ x,
                                              const int* __restrict__ lab,
                                              float* __restrict__ out) {
    int i = blockIdx.x * 4 + (threadIdx.x >> 5);   // 0..511
    int lane = threadIdx.x & 31;
    int c = lab[i];
    int n = g_cnt[c];
    if (i < n && n > 1) {
        int k = g_sorted[g_off[c] + i];
        const float4* xi = (const float4*)x + (size_t)i * 256;
        const float4* xk = (const float4*)x + (size_t)k * 256;
        const float4* sc = (const float4*)g_sums + (size_t)c * 256;
        float a_ii = 0.f, a_ik = 0.f, a_kk = 0.f, a_is = 0.f, a_ks = 0.f;
#pragma unroll
        for (int q = 0; q < 8; q++) {
            float4 vi = xi[q * 32 + lane];
            float4 vk = xk[q * 32 + lane];
            float4 vs = sc[q * 32 + lane];
            a_ii += vi.x * vi.x + vi.y * vi.y + vi.z * vi.z + vi.w * vi.w;
            a_ik += vi.x * vk.x + vi.y * vk.y + vi.z * vk.z + vi.w * vk.w;
            a_kk += vk.x * vk.x + vk.y * vk.y + vk.z * vk.z + vk.w * vk.w;
            a_is += vi.x * vs.x + vi.y * vs.y + vi.z * vs.z + vi.w * vs.w;
            a_ks += vk.x * vs.x + vk.y * vs.y + vk.z * vs.z + vk.w * vs.w;
        }
#pragma unroll
        for (int o = 16; o; o >>= 1) {
            a_ii += __shfl_xor_sync(0xFFFFFFFFu, a_ii, o);
            a_ik += __shfl_xor_sync(0xFFFFFFFFu, a_ik, o);
            a_kk += __shfl_xor_sync(0xFFFFFFFFu, a_kk, o);
            a_is += __shfl_xor_sync(0xFFFFFFFFu, a_is, o);
            a_ks += __shfl_xor_sync(0xFFFFFFFFu, a_ks, o);
        }
        if (lane == 0) {
            float inv_i = 1.0f / fmaxf(sqrtf(a_ii), EPSN);
            float inv_k = 1.0f / fmaxf(sqrtf(a_kk), EPSN);
            float s2 = g_s2[c];
            double nf2_i = (double)a_ii * inv_i * inv_i;
            double fiS   = (double)a_is * inv_i;
            double fifk  = (double)a_ik * inv_i * inv_k;
            double fkS   = (double)a_ks * inv_k;
            double nf2_k = (double)a_kk * inv_k * inv_k;
            double dn = (double)n;
            double base = (nf2_i - 2.0 * fiS / dn + (double)s2 / (dn * dn)) / (double)ND;
            double m = dn - 1.0;
            double fic  = (fiS - fifk) / m;
            double c2   = ((double)s2 - 2.0 * fkS + nf2_k) / (m * m);
            double excl = (nf2_i - 2.0 * fic + c2) / (double)ND;
            atomicAdd(&g_accum, excl - base);
        }
    }
    __threadfence();
    __syncthreads();
    __shared__ int islast;
    if (threadIdx.x == 0) islast = (atomicAdd(&g_done2, 1) == (int)gridDim.x - 1);
    __syncthreads();
    if (islast) {
        if (threadIdx.x == 0) {
            out[0] = (float)(LOSS_WEIGHT * g_accum / (double)NB);
            g_accum = 0.0;
            g_done2 = 0;
        }
        for (int u = threadIdx.x; u < NC; u += 128) g_cnt[u] = 0;
    }
}

extern "C" void kernel_launch(void* const* d_in, const int* in_sizes, int n_in,
                              void* d_out, int out_size) {
    const float* x   = (const float*)d_in[0];
    const int*   lab = (const int*)d_in[1];
    float* out = (float*)d_out;
    (void)in_sizes; (void)n_in; (void)out_size;

    k_pre<<<32, 1024>>>();                       // 1
    k_hist<<<NB / 1024, 1024>>>(lab);            // 2
    k_scatter<<<NB / 1024, 1024>>>(lab);         // 3
    k_fused<<<(NCHUNK + 3) / 4, 128>>>(x, lab);  // 4 -> profiled
    k_comb<<<NC, 256>>>();                       // 5
    k_corr<<<128, 128>>>(x, lab, out);           // 6
}